// round 8
// baseline (speedup 1.0000x reference)
#include <cuda_runtime.h>
#include <math.h>

#define M 8
#define N 8192
#define KC 256
#define ITERS 6
#define EPSILON 0.01f
#define GAMMA 0.005f
#define LOG2E 1.4426950408889634f

#define BLKS_PER_M 92
#define WARPS_PER_M (BLKS_PER_M * 4)

// ---------------- device scratch (static allocation only) ----------------
__device__ float g_L[M * KC];          // sum_n a
__device__ float g_W[M * 3 * KC];      // sum_n a * v   (no Q factor)
__device__ float g_S2v[M * KC];        // sum_n a * |v|^2
__device__ float4 g_X[KC];             // x,y,z,|x|^2
__device__ float g_Q[KC];
__device__ float g_R[M * 9];
__device__ float g_t[M * 3];
__device__ float g_beta;

__device__ __forceinline__ float ex2f(float x) {
    float y;
    asm("ex2.approx.ftz.f32 %0, %1;" : "=f"(y) : "f"(x));
    return y;
}

#define WSUM(v) do { \
    v += __shfl_xor_sync(0xffffffffu, (v), 16); \
    v += __shfl_xor_sync(0xffffffffu, (v), 8);  \
    v += __shfl_xor_sync(0xffffffffu, (v), 4);  \
    v += __shfl_xor_sync(0xffffffffu, (v), 2);  \
    v += __shfl_xor_sync(0xffffffffu, (v), 1);  \
} while (0)

// ---------------- init ----------------
__global__ void k_pre(const float* Vs, const float* X0, const float* Q0) {
    __shared__ float sh[256];
    int b = blockIdx.x, t = threadIdx.x;
    if (b < 24) {                      // b = m*3+d : mean over n -> g_t
        const float* p = Vs + b * N;
        float s = 0.f;
        for (int n = t; n < N; n += 256) s += p[n];
        sh[t] = s; __syncthreads();
        for (int o = 128; o > 0; o >>= 1) { if (t < o) sh[t] += sh[t + o]; __syncthreads(); }
        if (t == 0) g_t[b] = -sh[0] / (float)N;
    } else {
        float q = (t < KC) ? Q0[t] : 0.f;
        sh[t] = q; __syncthreads();
        for (int o = 128; o > 0; o >>= 1) { if (t < o) sh[t] += sh[t + o]; __syncthreads(); }
        if (t == 0) { float mq = sh[0] / (float)KC; g_beta = GAMMA * mq * sqrtf(mq); }
        if (t < KC) {
            float x = X0[t * 3 + 0], y = X0[t * 3 + 1], z = X0[t * 3 + 2];
            g_X[t] = make_float4(x, y, z, x * x + y * y + z * z);
            g_Q[t] = q;
        }
        if (t < 72) {                  // R = I per m
            int m = t / 9, i = t - 9 * m;
            g_R[t] = (i == 0 || i == 4 || i == 8) ? 1.f : 0.f;
        }
        for (int i = t; i < M * KC; i += 256) { g_L[i] = 0.f; g_S2v[i] = 0.f; }
        for (int i = t; i < M * 3 * KC; i += 256) g_W[i] = 0.f;
    }
}

// ------- a-pass: tv = R v + t on the fly; accumulate L, W, S2v only ------
// e = ex2( cx*tx + cy*ty + cz*tz + nq*rr + cc ), with q^1.5 folded into cc.
__global__ void __launch_bounds__(128, 5) k_apass(const float* __restrict__ Vs) {
    int lane = threadIdx.x & 31, warp = threadIdx.x >> 5;
    int m = blockIdx.x / BLKS_PER_M;
    int gw = (blockIdx.x - m * BLKS_PER_M) * 4 + warp;   // 0..WARPS_PER_M-1

    float cx[8], cy[8], cz[8], cc[8], nq[8];
#pragma unroll
    for (int j = 0; j < 8; j++) {
        int k = lane + (j << 5);
        float4 xx = g_X[k];
        float q = g_Q[k];
        float nhq = -0.5f * LOG2E * q;
        nq[j] = nhq;
        cx[j] = -2.f * nhq * xx.x; cy[j] = -2.f * nhq * xx.y; cz[j] = -2.f * nhq * xx.z;
        cc[j] = fmaf(nhq, xx.w, 1.5f * __log2f(q));
    }
    float beta = g_beta;
    float accL[8], aw0[8], aw1[8], aw2[8], aS[8];
#pragma unroll
    for (int j = 0; j < 8; j++) { accL[j] = 0.f; aw0[j] = 0.f; aw1[j] = 0.f; aw2[j] = 0.f; aS[j] = 0.f; }

    const float* vs = Vs + m * 3 * N;
    const float* Rm = g_R + m * 9;
    float r0 = Rm[0], r1 = Rm[1], r2c = Rm[2], r3 = Rm[3], r4 = Rm[4], r5 = Rm[5],
          r6 = Rm[6], r7 = Rm[7], r8 = Rm[8];
    float tt0 = g_t[m * 3 + 0], tt1 = g_t[m * 3 + 1], tt2 = g_t[m * 3 + 2];

#pragma unroll 2
    for (int n = gw; n < N; n += WARPS_PER_M) {
        float v0 = vs[n], v1 = vs[N + n], v2 = vs[2 * N + n];
        float tx = fmaf(r0, v0, fmaf(r1, v1, fmaf(r2c, v2, tt0)));
        float ty = fmaf(r3, v0, fmaf(r4, v1, fmaf(r5, v2, tt1)));
        float tz = fmaf(r6, v0, fmaf(r7, v1, fmaf(r8, v2, tt2)));
        float rr = fmaf(tx, tx, fmaf(ty, ty, tz * tz));
        float vv = fmaf(v0, v0, fmaf(v1, v1, v2 * v2));
        float ap[8];
#pragma unroll
        for (int j = 0; j < 8; j++) {
            float arg = fmaf(cx[j], tx, fmaf(cy[j], ty, fmaf(cz[j], tz, fmaf(nq[j], rr, cc[j]))));
            ap[j] = ex2f(arg);
        }
        float sA = (ap[0] + ap[1]) + (ap[2] + ap[3]);
        float sB = (ap[4] + ap[5]) + (ap[6] + ap[7]);
        float s = sA + sB;
        WSUM(s);
        float inv = __fdividef(1.f, s + beta);
#pragma unroll
        for (int j = 0; j < 8; j++) {
            float av = ap[j] * inv;
            accL[j] += av;
            aw0[j] = fmaf(v0, av, aw0[j]);
            aw1[j] = fmaf(v1, av, aw1[j]);
            aw2[j] = fmaf(v2, av, aw2[j]);
            aS[j]  = fmaf(vv, av, aS[j]);
        }
    }
    __shared__ float sh[5 * KC];
    for (int i = threadIdx.x; i < 5 * KC; i += 128) sh[i] = 0.f;
    __syncthreads();
#pragma unroll
    for (int j = 0; j < 8; j++) {
        int k = lane + (j << 5);
        atomicAdd(&sh[k], accL[j]);
        atomicAdd(&sh[KC + k], aw0[j]);
        atomicAdd(&sh[2 * KC + k], aw1[j]);
        atomicAdd(&sh[3 * KC + k], aw2[j]);
        atomicAdd(&sh[4 * KC + k], aS[j]);
    }
    __syncthreads();
    for (int i = threadIdx.x; i < KC; i += 128) {
        atomicAdd(&g_L[m * KC + i], sh[i]);
        atomicAdd(&g_W[(m * 3 + 0) * KC + i], sh[KC + i]);
        atomicAdd(&g_W[(m * 3 + 1) * KC + i], sh[2 * KC + i]);
        atomicAdd(&g_W[(m * 3 + 2) * KC + i], sh[3 * KC + i]);
        atomicAdd(&g_S2v[m * KC + i], sh[4 * KC + i]);
    }
}

// Jacobi rotation with COMPILE-TIME indices (keeps A/V in registers)
#define JROT(P_, Q_) do { \
    float apq = A[P_][Q_]; \
    if (fabsf(apq) > 1e-30f) { \
        float theta = 0.5f * (A[Q_][Q_] - A[P_][P_]) / apq; \
        float tj = copysignf(1.f, theta) / (fabsf(theta) + sqrtf(fmaf(theta, theta, 1.f))); \
        float c = rsqrtf(fmaf(tj, tj, 1.f)); \
        float sj = tj * c; \
        _Pragma("unroll") \
        for (int i_ = 0; i_ < 3; i_++) { \
            float aip = A[i_][P_], aiq = A[i_][Q_]; \
            A[i_][P_] = c * aip - sj * aiq; \
            A[i_][Q_] = sj * aip + c * aiq; \
        } \
        _Pragma("unroll") \
        for (int i_ = 0; i_ < 3; i_++) { \
            float api = A[P_][i_], aqi = A[Q_][i_]; \
            A[P_][i_] = c * api - sj * aqi; \
            A[Q_][i_] = sj * api + c * aqi; \
        } \
        _Pragma("unroll") \
        for (int i_ = 0; i_ < 3; i_++) { \
            float vip = V[i_][P_], viq = V[i_][Q_]; \
            V[i_][P_] = c * vip - sj * viq; \
            V[i_][Q_] = sj * vip + c * viq; \
        } \
    } \
} while (0)

#define VSWAPC(C0_, C1_) do { \
    float tmp_; \
    tmp_ = V[0][C0_]; V[0][C0_] = V[0][C1_]; V[0][C1_] = tmp_; \
    tmp_ = V[1][C0_]; V[1][C0_] = V[1][C1_]; V[1][C1_] = tmp_; \
    tmp_ = V[2][C0_]; V[2][C0_] = V[2][C1_]; V[2][C1_] = tmp_; \
} while (0)

// ---- solve: moments -> SVD -> R,t ; then per-k T/S2 -> X,Q update -------
__global__ void k_solve(int iter) {
    __shared__ float sR[M][9], st[M][3];
    int t = threadIdx.x;
    int lane = t & 31, m = t >> 5;   // warp m handles point set m
    float mW0 = 0, mW1 = 0, mW2 = 0, z = 0, mX0 = 0, mX1 = 0, mX2 = 0;
    float p[9];
#pragma unroll
    for (int i = 0; i < 9; i++) p[i] = 0.f;
#pragma unroll
    for (int j = 0; j < 8; j++) {
        int k = lane + (j << 5);
        float L = g_L[m * KC + k];
        float q = g_Q[k];
        float4 xx = g_X[k];
        float w0 = g_W[(m * 3 + 0) * KC + k] * q;
        float w1 = g_W[(m * 3 + 1) * KC + k] * q;
        float w2 = g_W[(m * 3 + 2) * KC + k] * q;
        mW0 += w0; mW1 += w1; mW2 += w2;
        float b = L * q; z += b;
        mX0 = fmaf(b, xx.x, mX0); mX1 = fmaf(b, xx.y, mX1); mX2 = fmaf(b, xx.z, mX2);
        p[0] = fmaf(w0, xx.x, p[0]); p[1] = fmaf(w1, xx.x, p[1]); p[2] = fmaf(w2, xx.x, p[2]);
        p[3] = fmaf(w0, xx.y, p[3]); p[4] = fmaf(w1, xx.y, p[4]); p[5] = fmaf(w2, xx.y, p[5]);
        p[6] = fmaf(w0, xx.z, p[6]); p[7] = fmaf(w1, xx.z, p[7]); p[8] = fmaf(w2, xx.z, p[8]);
    }
    WSUM(mW0); WSUM(mW1); WSUM(mW2); WSUM(z); WSUM(mX0); WSUM(mX1); WSUM(mX2);
#pragma unroll
    for (int i = 0; i < 9; i++) WSUM(p[i]);

    if (lane == 0) {
        float iz = 1.f / z;
        float mXa[3] = { mX0, mX1, mX2 }, mWa[3] = { mW0, mW1, mW2 };
        float P[3][3];
#pragma unroll
        for (int e = 0; e < 3; e++)
#pragma unroll
            for (int d = 0; d < 3; d++)
                P[e][d] = p[e * 3 + d] - mXa[e] * mWa[d] * iz;
        float A[3][3];
#pragma unroll
        for (int d1 = 0; d1 < 3; d1++)
#pragma unroll
            for (int d2 = 0; d2 < 3; d2++) {
                float s2 = 0.f;
#pragma unroll
                for (int e = 0; e < 3; e++) s2 += P[e][d1] * P[e][d2];
                A[d1][d2] = s2;
            }
        float V[3][3] = { {1, 0, 0}, {0, 1, 0}, {0, 0, 1} };
#pragma unroll
        for (int sweep = 0; sweep < 8; sweep++) {
            JROT(0, 1);
            JROT(0, 2);
            JROT(1, 2);
        }
        float e0 = A[0][0], e1 = A[1][1], e2 = A[2][2];
        if (e0 < e1) { float tm = e0; e0 = e1; e1 = tm; VSWAPC(0, 1); }
        if (e1 < e2) { float tm = e1; e1 = e2; e2 = tm; VSWAPC(1, 2); }
        if (e0 < e1) { float tm = e0; e0 = e1; e1 = tm; VSWAPC(0, 1); }
        float det = V[0][0] * (V[1][1] * V[2][2] - V[1][2] * V[2][1])
                  - V[0][1] * (V[1][0] * V[2][2] - V[1][2] * V[2][0])
                  + V[0][2] * (V[1][0] * V[2][1] - V[1][1] * V[2][0]);
        if (det < 0.f) { V[0][2] = -V[0][2]; V[1][2] = -V[1][2]; V[2][2] = -V[2][2]; }
        float u1[3], u2[3], u3[3];
#pragma unroll
        for (int e = 0; e < 3; e++) {
            u1[e] = P[e][0] * V[0][0] + P[e][1] * V[1][0] + P[e][2] * V[2][0];
            u2[e] = P[e][0] * V[0][1] + P[e][1] * V[1][1] + P[e][2] * V[2][1];
        }
        float n1 = rsqrtf(u1[0] * u1[0] + u1[1] * u1[1] + u1[2] * u1[2]);
#pragma unroll
        for (int e = 0; e < 3; e++) u1[e] *= n1;
        float d12 = u1[0] * u2[0] + u1[1] * u2[1] + u1[2] * u2[2];
#pragma unroll
        for (int e = 0; e < 3; e++) u2[e] -= d12 * u1[e];
        float n2 = rsqrtf(u2[0] * u2[0] + u2[1] * u2[1] + u2[2] * u2[2]);
#pragma unroll
        for (int e = 0; e < 3; e++) u2[e] *= n2;
        u3[0] = u1[1] * u2[2] - u1[2] * u2[1];
        u3[1] = u1[2] * u2[0] - u1[0] * u2[2];
        u3[2] = u1[0] * u2[1] - u1[1] * u2[0];
        float R[9];
#pragma unroll
        for (int i = 0; i < 3; i++)
#pragma unroll
            for (int jj = 0; jj < 3; jj++)
                R[i * 3 + jj] = u1[i] * V[jj][0] + u2[i] * V[jj][1] + u3[i] * V[jj][2];
#pragma unroll
        for (int i = 0; i < 9; i++) { g_R[m * 9 + i] = R[i]; sR[m][i] = R[i]; }
#pragma unroll
        for (int i = 0; i < 3; i++) {
            float tv = (mXa[i] - (R[i * 3 + 0] * mW0 + R[i * 3 + 1] * mW1 + R[i * 3 + 2] * mW2)) * iz;
            g_t[m * 3 + i] = tv; st[m][i] = tv;
        }
    }
    __syncthreads();

    // ---- per-k: den, T = sum_m (R Wraw + t L), S2; then X/Q update ----
    if (t < KC) {
        float den = 0.f, T0 = 0.f, T1 = 0.f, T2 = 0.f, S2 = 0.f;
#pragma unroll
        for (int mm = 0; mm < M; mm++) {
            float L  = g_L[mm * KC + t];
            float w0 = g_W[(mm * 3 + 0) * KC + t];
            float w1 = g_W[(mm * 3 + 1) * KC + t];
            float w2 = g_W[(mm * 3 + 2) * KC + t];
            float s2v = g_S2v[mm * KC + t];
            float t0 = st[mm][0], t1 = st[mm][1], t2 = st[mm][2];
            float rw0 = sR[mm][0] * w0 + sR[mm][1] * w1 + sR[mm][2] * w2;
            float rw1 = sR[mm][3] * w0 + sR[mm][4] * w1 + sR[mm][5] * w2;
            float rw2 = sR[mm][6] * w0 + sR[mm][7] * w1 + sR[mm][8] * w2;
            den += L;
            T0 += rw0 + t0 * L; T1 += rw1 + t1 * L; T2 += rw2 + t2 * L;
            S2 += s2v + 2.f * (t0 * rw0 + t1 * rw1 + t2 * rw2)
                + (t0 * t0 + t1 * t1 + t2 * t2) * L;
        }
        float inv = 1.f / den;
        float wn;
        if (iter > 1) {                          // FIX_CLUSTER_POS_ITER = 1
            float x = T0 * inv, y = T1 * inv, zz = T2 * inv;
            float xw = x * x + y * y + zz * zz;
            wn = S2 - (T0 * T0 + T1 * T1 + T2 * T2) * inv;
            g_X[t] = make_float4(x, y, zz, xw);
        } else {
            float4 xo = g_X[t];
            wn = fmaf(den, xo.w, S2) - 2.f * (xo.x * T0 + xo.y * T1 + xo.z * T2);
        }
        g_Q[t] = 3.f * den / (wn + 3.f * den * EPSILON);
    }
    __syncthreads();
    for (int i = t; i < M * KC; i += 256) { g_L[i] = 0.f; g_S2v[i] = 0.f; }
    for (int i = t; i < M * 3 * KC; i += 256) g_W[i] = 0.f;
}

// ---------------- gather outputs: concat(TVs, R, t, X) -------------------
__global__ void k_out(float* out, const float* __restrict__ Vs) {
    int idx = blockIdx.x * 256 + threadIdx.x;
    const int nTV = M * 3 * N, nR = M * 9, nT = M * 3, nX = KC * 3;
    if (idx < nTV) {
        int md = idx / N, n = idx - md * N;
        int m = md / 3, d = md - 3 * m;
        const float* v = Vs + m * 3 * N;
        const float* R = g_R + m * 9 + d * 3;
        out[idx] = fmaf(R[0], v[n], fmaf(R[1], v[N + n], fmaf(R[2], v[2 * N + n], g_t[md])));
    } else if (idx < nTV + nR) out[idx] = g_R[idx - nTV];
    else if (idx < nTV + nR + nT) out[idx] = g_t[idx - nTV - nR];
    else if (idx < nTV + nR + nT + nX) {
        int r = idx - nTV - nR - nT;
        int k = r / 3, d = r - 3 * k;
        float4 xx = g_X[k];
        out[idx] = (d == 0) ? xx.x : ((d == 1) ? xx.y : xx.z);
    }
}

extern "C" void kernel_launch(void* const* d_in, const int* in_sizes, int n_in,
                              void* d_out, int out_size) {
    const float* Vs = (const float*)d_in[0];
    const float* X0 = (const float*)d_in[1];
    const float* Q0 = (const float*)d_in[2];
    float* out = (float*)d_out;

    k_pre<<<25, 256>>>(Vs, X0, Q0);

    for (int i = 0; i < ITERS; i++) {
        k_apass<<<BLKS_PER_M * M, 128>>>(Vs);
        k_solve<<<1, 256>>>(i);
    }
    int total = M * 3 * N + M * 9 + M * 3 + KC * 3;
    k_out<<<(total + 255) / 256, 256>>>(out, Vs);
}

// round 11
// speedup vs baseline: 1.9520x; 1.9520x over previous
#include <cuda_runtime.h>
#include <math.h>

#define M 8
#define N 8192
#define KC 256
#define ITERS 6
#define EPSILON 0.01f
#define GAMMA 0.005f
#define LOG2E 1.4426950408889634f

#define BLKS_PER_M 64           // 64 blocks * 4 warps * 32 n = 8192 = N exactly

// ---------------- device scratch (static allocation only) ----------------
__device__ float g_L[M * KC];          // sum_n a
__device__ float g_W[M * 3 * KC];      // sum_n a * v   (no Q factor)
__device__ float g_S2v[M * KC];        // sum_n a * |v|^2
__device__ float4 g_X[KC];             // x,y,z,|x|^2
__device__ float g_Q[KC];
__device__ float g_R[M * 9];
__device__ float g_t[M * 3];
__device__ float g_beta;

__device__ __forceinline__ float ex2f(float x) {
    float y;
    asm("ex2.approx.ftz.f32 %0, %1;" : "=f"(y) : "f"(x));
    return y;
}

#define WSUM(v) do { \
    v += __shfl_xor_sync(0xffffffffu, (v), 16); \
    v += __shfl_xor_sync(0xffffffffu, (v), 8);  \
    v += __shfl_xor_sync(0xffffffffu, (v), 4);  \
    v += __shfl_xor_sync(0xffffffffu, (v), 2);  \
    v += __shfl_xor_sync(0xffffffffu, (v), 1);  \
} while (0)

// ---------------- init ----------------
__global__ void k_pre(const float* Vs, const float* X0, const float* Q0) {
    __shared__ float sh[256];
    int b = blockIdx.x, t = threadIdx.x;
    if (b < 24) {                      // b = m*3+d : mean over n -> g_t
        const float* p = Vs + b * N;
        float s = 0.f;
        for (int n = t; n < N; n += 256) s += p[n];
        sh[t] = s; __syncthreads();
        for (int o = 128; o > 0; o >>= 1) { if (t < o) sh[t] += sh[t + o]; __syncthreads(); }
        if (t == 0) g_t[b] = -sh[0] / (float)N;
    } else {
        float q = (t < KC) ? Q0[t] : 0.f;
        sh[t] = q; __syncthreads();
        for (int o = 128; o > 0; o >>= 1) { if (t < o) sh[t] += sh[t + o]; __syncthreads(); }
        if (t == 0) { float mq = sh[0] / (float)KC; g_beta = GAMMA * mq * sqrtf(mq); }
        if (t < KC) {
            float x = X0[t * 3 + 0], y = X0[t * 3 + 1], z = X0[t * 3 + 2];
            g_X[t] = make_float4(x, y, z, x * x + y * y + z * z);
            g_Q[t] = q;
        }
        if (t < 72) {                  // R = I per m
            int m = t / 9, i = t - 9 * m;
            g_R[t] = (i == 0 || i == 4 || i == 8) ? 1.f : 0.f;
        }
        for (int i = t; i < M * KC; i += 256) { g_L[i] = 0.f; g_S2v[i] = 0.f; }
        for (int i = t; i < M * 3 * KC; i += 256) g_W[i] = 0.f;
    }
}

// ------- a-pass, two-phase (no warp shuffles):
// Phase A: lane owns one n; loops all 256 k reading broadcast constants from
//          shared; accumulates softmax denominator per-lane.
// Phase B: lane owns 8 k (reg constants); loops the warp's 32 cached n's;
//          accumulates L, W, S2v in registers.
__global__ void __launch_bounds__(128) k_apass(const float* __restrict__ Vs) {
    int lane = threadIdx.x & 31, warp = threadIdx.x >> 5;
    int m = blockIdx.x >> 6;
    int blk = blockIdx.x & 63;

    __shared__ float4 sc4[KC];       // (cx, cy, cz, nq)
    __shared__ float  scc[KC];       // cc (includes 1.5*log2 q)
    __shared__ float4 sTV[128];      // (tx, ty, tz, rr) per n
    __shared__ float4 sV[128];       // (v0, v1, v2, vv) per n
    __shared__ float  sInv[128];     // 1/(sum+beta) per n
    __shared__ float  sh[5 * KC];    // block merge buffer

    // build constants in shared (once per block)
    for (int k = threadIdx.x; k < KC; k += 128) {
        float4 xx = g_X[k];
        float q = g_Q[k];
        float nhq = -0.5f * LOG2E * q;
        sc4[k] = make_float4(-2.f * nhq * xx.x, -2.f * nhq * xx.y, -2.f * nhq * xx.z, nhq);
        scc[k] = fmaf(nhq, xx.w, 1.5f * __log2f(q));
    }
    __syncthreads();

    float beta = g_beta;
    const float* vs = Vs + m * 3 * N;
    const float* Rm = g_R + m * 9;
    float r0 = Rm[0], r1 = Rm[1], r2c = Rm[2], r3 = Rm[3], r4 = Rm[4], r5 = Rm[5],
          r6 = Rm[6], r7 = Rm[7], r8 = Rm[8];
    float tt0 = g_t[m * 3 + 0], tt1 = g_t[m * 3 + 1], tt2 = g_t[m * 3 + 2];

    // ---- Phase A: per-lane n, per-lane denominator ----
    int nb = (blk * 4 + warp) << 5;          // warp's n-chunk base
    {
        int n = nb + lane;                   // coalesced loads
        float v0 = vs[n], v1 = vs[N + n], v2 = vs[2 * N + n];
        float tx = fmaf(r0, v0, fmaf(r1, v1, fmaf(r2c, v2, tt0)));
        float ty = fmaf(r3, v0, fmaf(r4, v1, fmaf(r5, v2, tt1)));
        float tz = fmaf(r6, v0, fmaf(r7, v1, fmaf(r8, v2, tt2)));
        float rr = fmaf(tx, tx, fmaf(ty, ty, tz * tz));
        float vv = fmaf(v0, v0, fmaf(v1, v1, v2 * v2));
        float s0 = 0.f, s1 = 0.f, s2 = 0.f, s3 = 0.f;
#pragma unroll 4
        for (int k = 0; k < KC; k += 4) {
            float4 cA = sc4[k + 0]; float ccA = scc[k + 0];
            float4 cB = sc4[k + 1]; float ccB = scc[k + 1];
            float4 cC = sc4[k + 2]; float ccC = scc[k + 2];
            float4 cD = sc4[k + 3]; float ccD = scc[k + 3];
            s0 += ex2f(fmaf(cA.x, tx, fmaf(cA.y, ty, fmaf(cA.z, tz, fmaf(cA.w, rr, ccA)))));
            s1 += ex2f(fmaf(cB.x, tx, fmaf(cB.y, ty, fmaf(cB.z, tz, fmaf(cB.w, rr, ccB)))));
            s2 += ex2f(fmaf(cC.x, tx, fmaf(cC.y, ty, fmaf(cC.z, tz, fmaf(cC.w, rr, ccC)))));
            s3 += ex2f(fmaf(cD.x, tx, fmaf(cD.y, ty, fmaf(cD.z, tz, fmaf(cD.w, rr, ccD)))));
        }
        float s = (s0 + s1) + (s2 + s3);
        int sl = (warp << 5) + lane;
        sTV[sl] = make_float4(tx, ty, tz, rr);
        sV[sl]  = make_float4(v0, v1, v2, vv);
        sInv[sl] = __fdividef(1.f, s + beta);
    }
    __syncwarp();

    // ---- Phase B: lane owns 8 k's, loop cached 32 n's ----
    float cx[8], cy[8], cz[8], cc[8], nq[8];
#pragma unroll
    for (int j = 0; j < 8; j++) {
        int k = lane + (j << 5);
        float4 c4 = sc4[k];
        cx[j] = c4.x; cy[j] = c4.y; cz[j] = c4.z; nq[j] = c4.w;
        cc[j] = scc[k];
    }
    float accL[8], aw0[8], aw1[8], aw2[8], aS[8];
#pragma unroll
    for (int j = 0; j < 8; j++) { accL[j] = 0.f; aw0[j] = 0.f; aw1[j] = 0.f; aw2[j] = 0.f; aS[j] = 0.f; }

#pragma unroll 2
    for (int ni = 0; ni < 32; ni++) {
        int sl = (warp << 5) + ni;
        float4 tvv = sTV[sl];            // broadcast
        float4 v4  = sV[sl];
        float inv  = sInv[sl];
        float tx = tvv.x, ty = tvv.y, tz = tvv.z, rr = tvv.w;
        float v0 = v4.x, v1 = v4.y, v2 = v4.z, vv = v4.w;
#pragma unroll
        for (int j = 0; j < 8; j++) {
            float arg = fmaf(cx[j], tx, fmaf(cy[j], ty, fmaf(cz[j], tz, fmaf(nq[j], rr, cc[j]))));
            float av = ex2f(arg) * inv;
            accL[j] += av;
            aw0[j] = fmaf(v0, av, aw0[j]);
            aw1[j] = fmaf(v1, av, aw1[j]);
            aw2[j] = fmaf(v2, av, aw2[j]);
            aS[j]  = fmaf(vv, av, aS[j]);
        }
    }

    // ---- block merge + global merge ----
    for (int i = threadIdx.x; i < 5 * KC; i += 128) sh[i] = 0.f;
    __syncthreads();
#pragma unroll
    for (int j = 0; j < 8; j++) {
        int k = lane + (j << 5);
        atomicAdd(&sh[k], accL[j]);
        atomicAdd(&sh[KC + k], aw0[j]);
        atomicAdd(&sh[2 * KC + k], aw1[j]);
        atomicAdd(&sh[3 * KC + k], aw2[j]);
        atomicAdd(&sh[4 * KC + k], aS[j]);
    }
    __syncthreads();
    for (int i = threadIdx.x; i < KC; i += 128) {
        atomicAdd(&g_L[m * KC + i], sh[i]);
        atomicAdd(&g_W[(m * 3 + 0) * KC + i], sh[KC + i]);
        atomicAdd(&g_W[(m * 3 + 1) * KC + i], sh[2 * KC + i]);
        atomicAdd(&g_W[(m * 3 + 2) * KC + i], sh[3 * KC + i]);
        atomicAdd(&g_S2v[m * KC + i], sh[4 * KC + i]);
    }
}

// Jacobi rotation with COMPILE-TIME indices (keeps A/V in registers)
#define JROT(P_, Q_) do { \
    float apq = A[P_][Q_]; \
    if (fabsf(apq) > 1e-30f) { \
        float theta = 0.5f * (A[Q_][Q_] - A[P_][P_]) / apq; \
        float tj = copysignf(1.f, theta) / (fabsf(theta) + sqrtf(fmaf(theta, theta, 1.f))); \
        float c = rsqrtf(fmaf(tj, tj, 1.f)); \
        float sj = tj * c; \
        _Pragma("unroll") \
        for (int i_ = 0; i_ < 3; i_++) { \
            float aip = A[i_][P_], aiq = A[i_][Q_]; \
            A[i_][P_] = c * aip - sj * aiq; \
            A[i_][Q_] = sj * aip + c * aiq; \
        } \
        _Pragma("unroll") \
        for (int i_ = 0; i_ < 3; i_++) { \
            float api = A[P_][i_], aqi = A[Q_][i_]; \
            A[P_][i_] = c * api - sj * aqi; \
            A[Q_][i_] = sj * api + c * aqi; \
        } \
        _Pragma("unroll") \
        for (int i_ = 0; i_ < 3; i_++) { \
            float vip = V[i_][P_], viq = V[i_][Q_]; \
            V[i_][P_] = c * vip - sj * viq; \
            V[i_][Q_] = sj * vip + c * viq; \
        } \
    } \
} while (0)

#define VSWAPC(C0_, C1_) do { \
    float tmp_; \
    tmp_ = V[0][C0_]; V[0][C0_] = V[0][C1_]; V[0][C1_] = tmp_; \
    tmp_ = V[1][C0_]; V[1][C0_] = V[1][C1_]; V[1][C1_] = tmp_; \
    tmp_ = V[2][C0_]; V[2][C0_] = V[2][C1_]; V[2][C1_] = tmp_; \
} while (0)

// ---- solve: moments -> SVD -> R,t ; then per-k T/S2 -> X,Q update -------
__global__ void k_solve(int iter) {
    __shared__ float sR[M][9], st[M][3];
    int t = threadIdx.x;
    int lane = t & 31, m = t >> 5;   // warp m handles point set m
    float mW0 = 0, mW1 = 0, mW2 = 0, z = 0, mX0 = 0, mX1 = 0, mX2 = 0;
    float p[9];
#pragma unroll
    for (int i = 0; i < 9; i++) p[i] = 0.f;
#pragma unroll
    for (int j = 0; j < 8; j++) {
        int k = lane + (j << 5);
        float L = g_L[m * KC + k];
        float q = g_Q[k];
        float4 xx = g_X[k];
        float w0 = g_W[(m * 3 + 0) * KC + k] * q;
        float w1 = g_W[(m * 3 + 1) * KC + k] * q;
        float w2 = g_W[(m * 3 + 2) * KC + k] * q;
        mW0 += w0; mW1 += w1; mW2 += w2;
        float b = L * q; z += b;
        mX0 = fmaf(b, xx.x, mX0); mX1 = fmaf(b, xx.y, mX1); mX2 = fmaf(b, xx.z, mX2);
        p[0] = fmaf(w0, xx.x, p[0]); p[1] = fmaf(w1, xx.x, p[1]); p[2] = fmaf(w2, xx.x, p[2]);
        p[3] = fmaf(w0, xx.y, p[3]); p[4] = fmaf(w1, xx.y, p[4]); p[5] = fmaf(w2, xx.y, p[5]);
        p[6] = fmaf(w0, xx.z, p[6]); p[7] = fmaf(w1, xx.z, p[7]); p[8] = fmaf(w2, xx.z, p[8]);
    }
    WSUM(mW0); WSUM(mW1); WSUM(mW2); WSUM(z); WSUM(mX0); WSUM(mX1); WSUM(mX2);
#pragma unroll
    for (int i = 0; i < 9; i++) WSUM(p[i]);

    if (lane == 0) {
        float iz = 1.f / z;
        float mXa[3] = { mX0, mX1, mX2 }, mWa[3] = { mW0, mW1, mW2 };
        float P[3][3];
#pragma unroll
        for (int e = 0; e < 3; e++)
#pragma unroll
            for (int d = 0; d < 3; d++)
                P[e][d] = p[e * 3 + d] - mXa[e] * mWa[d] * iz;
        float A[3][3];
#pragma unroll
        for (int d1 = 0; d1 < 3; d1++)
#pragma unroll
            for (int d2 = 0; d2 < 3; d2++) {
                float s2 = 0.f;
#pragma unroll
                for (int e = 0; e < 3; e++) s2 += P[e][d1] * P[e][d2];
                A[d1][d2] = s2;
            }
        float V[3][3] = { {1, 0, 0}, {0, 1, 0}, {0, 0, 1} };
#pragma unroll
        for (int sweep = 0; sweep < 8; sweep++) {
            JROT(0, 1);
            JROT(0, 2);
            JROT(1, 2);
        }
        float e0 = A[0][0], e1 = A[1][1], e2 = A[2][2];
        if (e0 < e1) { float tm = e0; e0 = e1; e1 = tm; VSWAPC(0, 1); }
        if (e1 < e2) { float tm = e1; e1 = e2; e2 = tm; VSWAPC(1, 2); }
        if (e0 < e1) { float tm = e0; e0 = e1; e1 = tm; VSWAPC(0, 1); }
        float det = V[0][0] * (V[1][1] * V[2][2] - V[1][2] * V[2][1])
                  - V[0][1] * (V[1][0] * V[2][2] - V[1][2] * V[2][0])
                  + V[0][2] * (V[1][0] * V[2][1] - V[1][1] * V[2][0]);
        if (det < 0.f) { V[0][2] = -V[0][2]; V[1][2] = -V[1][2]; V[2][2] = -V[2][2]; }
        float u1[3], u2[3], u3[3];
#pragma unroll
        for (int e = 0; e < 3; e++) {
            u1[e] = P[e][0] * V[0][0] + P[e][1] * V[1][0] + P[e][2] * V[2][0];
            u2[e] = P[e][0] * V[0][1] + P[e][1] * V[1][1] + P[e][2] * V[2][1];
        }
        float n1 = rsqrtf(u1[0] * u1[0] + u1[1] * u1[1] + u1[2] * u1[2]);
#pragma unroll
        for (int e = 0; e < 3; e++) u1[e] *= n1;
        float d12 = u1[0] * u2[0] + u1[1] * u2[1] + u1[2] * u2[2];
#pragma unroll
        for (int e = 0; e < 3; e++) u2[e] -= d12 * u1[e];
        float n2 = rsqrtf(u2[0] * u2[0] + u2[1] * u2[1] + u2[2] * u2[2]);
#pragma unroll
        for (int e = 0; e < 3; e++) u2[e] *= n2;
        u3[0] = u1[1] * u2[2] - u1[2] * u2[1];
        u3[1] = u1[2] * u2[0] - u1[0] * u2[2];
        u3[2] = u1[0] * u2[1] - u1[1] * u2[0];
        float R[9];
#pragma unroll
        for (int i = 0; i < 3; i++)
#pragma unroll
            for (int jj = 0; jj < 3; jj++)
                R[i * 3 + jj] = u1[i] * V[jj][0] + u2[i] * V[jj][1] + u3[i] * V[jj][2];
#pragma unroll
        for (int i = 0; i < 9; i++) { g_R[m * 9 + i] = R[i]; sR[m][i] = R[i]; }
#pragma unroll
        for (int i = 0; i < 3; i++) {
            float tv = (mXa[i] - (R[i * 3 + 0] * mW0 + R[i * 3 + 1] * mW1 + R[i * 3 + 2] * mW2)) * iz;
            g_t[m * 3 + i] = tv; st[m][i] = tv;
        }
    }
    __syncthreads();

    // ---- per-k: den, T = sum_m (R Wraw + t L), S2; then X/Q update ----
    if (t < KC) {
        float den = 0.f, T0 = 0.f, T1 = 0.f, T2 = 0.f, S2 = 0.f;
#pragma unroll
        for (int mm = 0; mm < M; mm++) {
            float L  = g_L[mm * KC + t];
            float w0 = g_W[(mm * 3 + 0) * KC + t];
            float w1 = g_W[(mm * 3 + 1) * KC + t];
            float w2 = g_W[(mm * 3 + 2) * KC + t];
            float s2v = g_S2v[mm * KC + t];
            float t0 = st[mm][0], t1 = st[mm][1], t2 = st[mm][2];
            float rw0 = sR[mm][0] * w0 + sR[mm][1] * w1 + sR[mm][2] * w2;
            float rw1 = sR[mm][3] * w0 + sR[mm][4] * w1 + sR[mm][5] * w2;
            float rw2 = sR[mm][6] * w0 + sR[mm][7] * w1 + sR[mm][8] * w2;
            den += L;
            T0 += rw0 + t0 * L; T1 += rw1 + t1 * L; T2 += rw2 + t2 * L;
            S2 += s2v + 2.f * (t0 * rw0 + t1 * rw1 + t2 * rw2)
                + (t0 * t0 + t1 * t1 + t2 * t2) * L;
        }
        float inv = 1.f / den;
        float wn;
        if (iter > 1) {                          // FIX_CLUSTER_POS_ITER = 1
            float x = T0 * inv, y = T1 * inv, zz = T2 * inv;
            float xw = x * x + y * y + zz * zz;
            wn = S2 - (T0 * T0 + T1 * T1 + T2 * T2) * inv;
            g_X[t] = make_float4(x, y, zz, xw);
        } else {
            float4 xo = g_X[t];
            wn = fmaf(den, xo.w, S2) - 2.f * (xo.x * T0 + xo.y * T1 + xo.z * T2);
        }
        g_Q[t] = 3.f * den / (wn + 3.f * den * EPSILON);
    }
    __syncthreads();
    for (int i = t; i < M * KC; i += 256) { g_L[i] = 0.f; g_S2v[i] = 0.f; }
    for (int i = t; i < M * 3 * KC; i += 256) g_W[i] = 0.f;
}

// ---------------- gather outputs: concat(TVs, R, t, X) -------------------
__global__ void k_out(float* out, const float* __restrict__ Vs) {
    int idx = blockIdx.x * 256 + threadIdx.x;
    const int nTV = M * 3 * N, nR = M * 9, nT = M * 3, nX = KC * 3;
    if (idx < nTV) {
        int md = idx / N, n = idx - md * N;
        int m = md / 3, d = md - 3 * m;
        const float* v = Vs + m * 3 * N;
        const float* R = g_R + m * 9 + d * 3;
        out[idx] = fmaf(R[0], v[n], fmaf(R[1], v[N + n], fmaf(R[2], v[2 * N + n], g_t[md])));
    } else if (idx < nTV + nR) out[idx] = g_R[idx - nTV];
    else if (idx < nTV + nR + nT) out[idx] = g_t[idx - nTV - nR];
    else if (idx < nTV + nR + nT + nX) {
        int r = idx - nTV - nR - nT;
        int k = r / 3, d = r - 3 * k;
        float4 xx = g_X[k];
        out[idx] = (d == 0) ? xx.x : ((d == 1) ? xx.y : xx.z);
    }
}

extern "C" void kernel_launch(void* const* d_in, const int* in_sizes, int n_in,
                              void* d_out, int out_size) {
    const float* Vs = (const float*)d_in[0];
    const float* X0 = (const float*)d_in[1];
    const float* Q0 = (const float*)d_in[2];
    float* out = (float*)d_out;

    k_pre<<<25, 256>>>(Vs, X0, Q0);

    for (int i = 0; i < ITERS; i++) {
        k_apass<<<BLKS_PER_M * M, 128>>>(Vs);
        k_solve<<<1, 256>>>(i);
    }
    int total = M * 3 * N + M * 9 + M * 3 + KC * 3;
    k_out<<<(total + 255) / 256, 256>>>(out, Vs);
}

// round 12
// speedup vs baseline: 1.9609x; 1.0045x over previous
#include <cuda_runtime.h>
#include <math.h>

#define M 8
#define N 8192
#define KC 256
#define ITERS 6
#define EPSILON 0.01f
#define GAMMA 0.005f
#define LOG2E 1.4426950408889634f

#define BLKS_PER_M 74           // 74 * 8 = 592 = 4 CTAs on every of 148 SMs
#define WPM (BLKS_PER_M * 4)    // 296 warps per m
#define NREM (N - WPM * 27)     // 200 warps carry 28 points, rest 27
#define MAXC 28

// ---------------- device scratch (static allocation only) ----------------
__device__ float g_L[M * KC];          // sum_n a
__device__ float g_W[M * 3 * KC];      // sum_n a * v   (no Q factor)
__device__ float g_S2v[M * KC];        // sum_n a * |v|^2
__device__ float4 g_X[KC];             // x,y,z,|x|^2
__device__ float g_Q[KC];
__device__ float g_R[M * 9];
__device__ float g_t[M * 3];
__device__ float g_beta;

__device__ __forceinline__ float ex2f(float x) {
    float y;
    asm("ex2.approx.ftz.f32 %0, %1;" : "=f"(y) : "f"(x));
    return y;
}

#define WSUM(v) do { \
    v += __shfl_xor_sync(0xffffffffu, (v), 16); \
    v += __shfl_xor_sync(0xffffffffu, (v), 8);  \
    v += __shfl_xor_sync(0xffffffffu, (v), 4);  \
    v += __shfl_xor_sync(0xffffffffu, (v), 2);  \
    v += __shfl_xor_sync(0xffffffffu, (v), 1);  \
} while (0)

// ---------------- init ----------------
__global__ void k_pre(const float* Vs, const float* X0, const float* Q0) {
    __shared__ float sh[256];
    int b = blockIdx.x, t = threadIdx.x;
    if (b < 24) {                      // b = m*3+d : mean over n -> g_t
        const float* p = Vs + b * N;
        float s = 0.f;
        for (int n = t; n < N; n += 256) s += p[n];
        sh[t] = s; __syncthreads();
        for (int o = 128; o > 0; o >>= 1) { if (t < o) sh[t] += sh[t + o]; __syncthreads(); }
        if (t == 0) g_t[b] = -sh[0] / (float)N;
    } else {
        float q = (t < KC) ? Q0[t] : 0.f;
        sh[t] = q; __syncthreads();
        for (int o = 128; o > 0; o >>= 1) { if (t < o) sh[t] += sh[t + o]; __syncthreads(); }
        if (t == 0) { float mq = sh[0] / (float)KC; g_beta = GAMMA * mq * sqrtf(mq); }
        if (t < KC) {
            float x = X0[t * 3 + 0], y = X0[t * 3 + 1], z = X0[t * 3 + 2];
            g_X[t] = make_float4(x, y, z, x * x + y * y + z * z);
            g_Q[t] = q;
        }
        if (t < 72) {                  // R = I per m
            int m = t / 9, i = t - 9 * m;
            g_R[t] = (i == 0 || i == 4 || i == 8) ? 1.f : 0.f;
        }
        for (int i = t; i < M * KC; i += 256) { g_L[i] = 0.f; g_S2v[i] = 0.f; }
        for (int i = t; i < M * 3 * KC; i += 256) g_W[i] = 0.f;
    }
}

// ------- a-pass, two-phase (no warp shuffles):
// Phase A: lane owns one n; loops all 256 k reading broadcast constants from
//          shared; accumulates softmax denominator per-lane.
// Phase B: two sequential halves of 4 k each (keeps register peak ~80 so the
//          (128,6) launch bound holds 6 CTAs/SM); loops the warp's cached n's.
__global__ void __launch_bounds__(128, 6) k_apass(const float* __restrict__ Vs) {
    int lane = threadIdx.x & 31, warp = threadIdx.x >> 5;
    int m = blockIdx.x / BLKS_PER_M;
    int blk = blockIdx.x - m * BLKS_PER_M;
    int gw = blk * 4 + warp;                         // 0..WPM-1
    int cnt = (gw < NREM) ? 28 : 27;
    int start = gw * 27 + min(gw, NREM);

    __shared__ float4 sc4[KC];       // (cx, cy, cz, nq)
    __shared__ float  scc[KC];       // cc (includes 1.5*log2 q)
    __shared__ float4 sTV[4 * MAXC]; // (tx, ty, tz, rr) per n
    __shared__ float4 sV[4 * MAXC];  // (v0, v1, v2, vv) per n
    __shared__ float  sInv[4 * MAXC];
    __shared__ float  sh[5 * KC];    // block merge buffer

    // build constants in shared (once per block)
    for (int k = threadIdx.x; k < KC; k += 128) {
        float4 xx = g_X[k];
        float q = g_Q[k];
        float nhq = -0.5f * LOG2E * q;
        sc4[k] = make_float4(-2.f * nhq * xx.x, -2.f * nhq * xx.y, -2.f * nhq * xx.z, nhq);
        scc[k] = fmaf(nhq, xx.w, 1.5f * __log2f(q));
    }
    for (int i = threadIdx.x; i < 5 * KC; i += 128) sh[i] = 0.f;
    __syncthreads();

    float beta = g_beta;
    const float* vs = Vs + m * 3 * N;
    const float* Rm = g_R + m * 9;
    float r0 = Rm[0], r1 = Rm[1], r2c = Rm[2], r3 = Rm[3], r4 = Rm[4], r5 = Rm[5],
          r6 = Rm[6], r7 = Rm[7], r8 = Rm[8];
    float tt0 = g_t[m * 3 + 0], tt1 = g_t[m * 3 + 1], tt2 = g_t[m * 3 + 2];

    // ---- Phase A: per-lane n, per-lane denominator ----
    {
        int n = start + min(lane, cnt - 1);          // clamped (no OOB)
        float v0 = vs[n], v1 = vs[N + n], v2 = vs[2 * N + n];
        float tx = fmaf(r0, v0, fmaf(r1, v1, fmaf(r2c, v2, tt0)));
        float ty = fmaf(r3, v0, fmaf(r4, v1, fmaf(r5, v2, tt1)));
        float tz = fmaf(r6, v0, fmaf(r7, v1, fmaf(r8, v2, tt2)));
        float rr = fmaf(tx, tx, fmaf(ty, ty, tz * tz));
        float vv = fmaf(v0, v0, fmaf(v1, v1, v2 * v2));
        float s0 = 0.f, s1 = 0.f, s2 = 0.f, s3 = 0.f;
#pragma unroll 4
        for (int k = 0; k < KC; k += 4) {
            float4 cA = sc4[k + 0]; float ccA = scc[k + 0];
            float4 cB = sc4[k + 1]; float ccB = scc[k + 1];
            float4 cC = sc4[k + 2]; float ccC = scc[k + 2];
            float4 cD = sc4[k + 3]; float ccD = scc[k + 3];
            s0 += ex2f(fmaf(cA.x, tx, fmaf(cA.y, ty, fmaf(cA.z, tz, fmaf(cA.w, rr, ccA)))));
            s1 += ex2f(fmaf(cB.x, tx, fmaf(cB.y, ty, fmaf(cB.z, tz, fmaf(cB.w, rr, ccB)))));
            s2 += ex2f(fmaf(cC.x, tx, fmaf(cC.y, ty, fmaf(cC.z, tz, fmaf(cC.w, rr, ccC)))));
            s3 += ex2f(fmaf(cD.x, tx, fmaf(cD.y, ty, fmaf(cD.z, tz, fmaf(cD.w, rr, ccD)))));
        }
        float s = (s0 + s1) + (s2 + s3);
        if (lane < cnt) {
            int sl = warp * MAXC + lane;
            sTV[sl] = make_float4(tx, ty, tz, rr);
            sV[sl]  = make_float4(v0, v1, v2, vv);
            sInv[sl] = __fdividef(1.f, s + beta);
        }
    }
    __syncwarp();

    // ---- Phase B: two halves of 4 k per lane ----
#pragma unroll 1
    for (int half = 0; half < 2; half++) {
        float cx[4], cy[4], cz[4], nq[4], cc[4];
#pragma unroll
        for (int j = 0; j < 4; j++) {
            int k = lane + ((half * 4 + j) << 5);
            float4 c4 = sc4[k];
            cx[j] = c4.x; cy[j] = c4.y; cz[j] = c4.z; nq[j] = c4.w;
            cc[j] = scc[k];
        }
        float accL[4], aw0[4], aw1[4], aw2[4], aS[4];
#pragma unroll
        for (int j = 0; j < 4; j++) { accL[j] = 0.f; aw0[j] = 0.f; aw1[j] = 0.f; aw2[j] = 0.f; aS[j] = 0.f; }

#pragma unroll 2
        for (int ni = 0; ni < cnt; ni++) {
            int sl = warp * MAXC + ni;
            float4 tvv = sTV[sl];            // broadcast
            float4 v4  = sV[sl];
            float inv  = sInv[sl];
            float tx = tvv.x, ty = tvv.y, tz = tvv.z, rr = tvv.w;
            float v0 = v4.x, v1 = v4.y, v2 = v4.z, vv = v4.w;
#pragma unroll
            for (int j = 0; j < 4; j++) {
                float arg = fmaf(cx[j], tx, fmaf(cy[j], ty, fmaf(cz[j], tz, fmaf(nq[j], rr, cc[j]))));
                float av = ex2f(arg) * inv;
                accL[j] += av;
                aw0[j] = fmaf(v0, av, aw0[j]);
                aw1[j] = fmaf(v1, av, aw1[j]);
                aw2[j] = fmaf(v2, av, aw2[j]);
                aS[j]  = fmaf(vv, av, aS[j]);
            }
        }
#pragma unroll
        for (int j = 0; j < 4; j++) {
            int k = lane + ((half * 4 + j) << 5);
            atomicAdd(&sh[k], accL[j]);
            atomicAdd(&sh[KC + k], aw0[j]);
            atomicAdd(&sh[2 * KC + k], aw1[j]);
            atomicAdd(&sh[3 * KC + k], aw2[j]);
            atomicAdd(&sh[4 * KC + k], aS[j]);
        }
    }
    __syncthreads();

    // ---- global merge ----
    for (int i = threadIdx.x; i < KC; i += 128) {
        atomicAdd(&g_L[m * KC + i], sh[i]);
        atomicAdd(&g_W[(m * 3 + 0) * KC + i], sh[KC + i]);
        atomicAdd(&g_W[(m * 3 + 1) * KC + i], sh[2 * KC + i]);
        atomicAdd(&g_W[(m * 3 + 2) * KC + i], sh[3 * KC + i]);
        atomicAdd(&g_S2v[m * KC + i], sh[4 * KC + i]);
    }
}

// Jacobi rotation with COMPILE-TIME indices (keeps A/V in registers)
#define JROT(P_, Q_) do { \
    float apq = A[P_][Q_]; \
    if (fabsf(apq) > 1e-30f) { \
        float theta = 0.5f * (A[Q_][Q_] - A[P_][P_]) / apq; \
        float tj = copysignf(1.f, theta) / (fabsf(theta) + sqrtf(fmaf(theta, theta, 1.f))); \
        float c = rsqrtf(fmaf(tj, tj, 1.f)); \
        float sj = tj * c; \
        _Pragma("unroll") \
        for (int i_ = 0; i_ < 3; i_++) { \
            float aip = A[i_][P_], aiq = A[i_][Q_]; \
            A[i_][P_] = c * aip - sj * aiq; \
            A[i_][Q_] = sj * aip + c * aiq; \
        } \
        _Pragma("unroll") \
        for (int i_ = 0; i_ < 3; i_++) { \
            float api = A[P_][i_], aqi = A[Q_][i_]; \
            A[P_][i_] = c * api - sj * aqi; \
            A[Q_][i_] = sj * api + c * aqi; \
        } \
        _Pragma("unroll") \
        for (int i_ = 0; i_ < 3; i_++) { \
            float vip = V[i_][P_], viq = V[i_][Q_]; \
            V[i_][P_] = c * vip - sj * viq; \
            V[i_][Q_] = sj * vip + c * viq; \
        } \
    } \
} while (0)

#define VSWAPC(C0_, C1_) do { \
    float tmp_; \
    tmp_ = V[0][C0_]; V[0][C0_] = V[0][C1_]; V[0][C1_] = tmp_; \
    tmp_ = V[1][C0_]; V[1][C0_] = V[1][C1_]; V[1][C1_] = tmp_; \
    tmp_ = V[2][C0_]; V[2][C0_] = V[2][C1_]; V[2][C1_] = tmp_; \
} while (0)

// ---- solve: moments -> SVD -> R,t ; then per-k T/S2 -> X,Q update -------
__global__ void k_solve(int iter) {
    __shared__ float sR[M][9], st[M][3];
    int t = threadIdx.x;
    int lane = t & 31, m = t >> 5;   // warp m handles point set m
    float mW0 = 0, mW1 = 0, mW2 = 0, z = 0, mX0 = 0, mX1 = 0, mX2 = 0;
    float p[9];
#pragma unroll
    for (int i = 0; i < 9; i++) p[i] = 0.f;
#pragma unroll
    for (int j = 0; j < 8; j++) {
        int k = lane + (j << 5);
        float L = g_L[m * KC + k];
        float q = g_Q[k];
        float4 xx = g_X[k];
        float w0 = g_W[(m * 3 + 0) * KC + k] * q;
        float w1 = g_W[(m * 3 + 1) * KC + k] * q;
        float w2 = g_W[(m * 3 + 2) * KC + k] * q;
        mW0 += w0; mW1 += w1; mW2 += w2;
        float b = L * q; z += b;
        mX0 = fmaf(b, xx.x, mX0); mX1 = fmaf(b, xx.y, mX1); mX2 = fmaf(b, xx.z, mX2);
        p[0] = fmaf(w0, xx.x, p[0]); p[1] = fmaf(w1, xx.x, p[1]); p[2] = fmaf(w2, xx.x, p[2]);
        p[3] = fmaf(w0, xx.y, p[3]); p[4] = fmaf(w1, xx.y, p[4]); p[5] = fmaf(w2, xx.y, p[5]);
        p[6] = fmaf(w0, xx.z, p[6]); p[7] = fmaf(w1, xx.z, p[7]); p[8] = fmaf(w2, xx.z, p[8]);
    }
    WSUM(mW0); WSUM(mW1); WSUM(mW2); WSUM(z); WSUM(mX0); WSUM(mX1); WSUM(mX2);
#pragma unroll
    for (int i = 0; i < 9; i++) WSUM(p[i]);

    if (lane == 0) {
        float iz = 1.f / z;
        float mXa[3] = { mX0, mX1, mX2 }, mWa[3] = { mW0, mW1, mW2 };
        float P[3][3];
#pragma unroll
        for (int e = 0; e < 3; e++)
#pragma unroll
            for (int d = 0; d < 3; d++)
                P[e][d] = p[e * 3 + d] - mXa[e] * mWa[d] * iz;
        float A[3][3];
#pragma unroll
        for (int d1 = 0; d1 < 3; d1++)
#pragma unroll
            for (int d2 = 0; d2 < 3; d2++) {
                float s2 = 0.f;
#pragma unroll
                for (int e = 0; e < 3; e++) s2 += P[e][d1] * P[e][d2];
                A[d1][d2] = s2;
            }
        float V[3][3] = { {1, 0, 0}, {0, 1, 0}, {0, 0, 1} };
#pragma unroll
        for (int sweep = 0; sweep < 8; sweep++) {
            JROT(0, 1);
            JROT(0, 2);
            JROT(1, 2);
        }
        float e0 = A[0][0], e1 = A[1][1], e2 = A[2][2];
        if (e0 < e1) { float tm = e0; e0 = e1; e1 = tm; VSWAPC(0, 1); }
        if (e1 < e2) { float tm = e1; e1 = e2; e2 = tm; VSWAPC(1, 2); }
        if (e0 < e1) { float tm = e0; e0 = e1; e1 = tm; VSWAPC(0, 1); }
        float det = V[0][0] * (V[1][1] * V[2][2] - V[1][2] * V[2][1])
                  - V[0][1] * (V[1][0] * V[2][2] - V[1][2] * V[2][0])
                  + V[0][2] * (V[1][0] * V[2][1] - V[1][1] * V[2][0]);
        if (det < 0.f) { V[0][2] = -V[0][2]; V[1][2] = -V[1][2]; V[2][2] = -V[2][2]; }
        float u1[3], u2[3], u3[3];
#pragma unroll
        for (int e = 0; e < 3; e++) {
            u1[e] = P[e][0] * V[0][0] + P[e][1] * V[1][0] + P[e][2] * V[2][0];
            u2[e] = P[e][0] * V[0][1] + P[e][1] * V[1][1] + P[e][2] * V[2][1];
        }
        float n1 = rsqrtf(u1[0] * u1[0] + u1[1] * u1[1] + u1[2] * u1[2]);
#pragma unroll
        for (int e = 0; e < 3; e++) u1[e] *= n1;
        float d12 = u1[0] * u2[0] + u1[1] * u2[1] + u1[2] * u2[2];
#pragma unroll
        for (int e = 0; e < 3; e++) u2[e] -= d12 * u1[e];
        float n2 = rsqrtf(u2[0] * u2[0] + u2[1] * u2[1] + u2[2] * u2[2]);
#pragma unroll
        for (int e = 0; e < 3; e++) u2[e] *= n2;
        u3[0] = u1[1] * u2[2] - u1[2] * u2[1];
        u3[1] = u1[2] * u2[0] - u1[0] * u2[2];
        u3[2] = u1[0] * u2[1] - u1[1] * u2[0];
        float R[9];
#pragma unroll
        for (int i = 0; i < 3; i++)
#pragma unroll
            for (int jj = 0; jj < 3; jj++)
                R[i * 3 + jj] = u1[i] * V[jj][0] + u2[i] * V[jj][1] + u3[i] * V[jj][2];
#pragma unroll
        for (int i = 0; i < 9; i++) { g_R[m * 9 + i] = R[i]; sR[m][i] = R[i]; }
#pragma unroll
        for (int i = 0; i < 3; i++) {
            float tv = (mXa[i] - (R[i * 3 + 0] * mW0 + R[i * 3 + 1] * mW1 + R[i * 3 + 2] * mW2)) * iz;
            g_t[m * 3 + i] = tv; st[m][i] = tv;
        }
    }
    __syncthreads();

    // ---- per-k: den, T = sum_m (R Wraw + t L), S2; then X/Q update ----
    if (t < KC) {
        float den = 0.f, T0 = 0.f, T1 = 0.f, T2 = 0.f, S2 = 0.f;
#pragma unroll
        for (int mm = 0; mm < M; mm++) {
            float L  = g_L[mm * KC + t];
            float w0 = g_W[(mm * 3 + 0) * KC + t];
            float w1 = g_W[(mm * 3 + 1) * KC + t];
            float w2 = g_W[(mm * 3 + 2) * KC + t];
            float s2v = g_S2v[mm * KC + t];
            float t0 = st[mm][0], t1 = st[mm][1], t2 = st[mm][2];
            float rw0 = sR[mm][0] * w0 + sR[mm][1] * w1 + sR[mm][2] * w2;
            float rw1 = sR[mm][3] * w0 + sR[mm][4] * w1 + sR[mm][5] * w2;
            float rw2 = sR[mm][6] * w0 + sR[mm][7] * w1 + sR[mm][8] * w2;
            den += L;
            T0 += rw0 + t0 * L; T1 += rw1 + t1 * L; T2 += rw2 + t2 * L;
            S2 += s2v + 2.f * (t0 * rw0 + t1 * rw1 + t2 * rw2)
                + (t0 * t0 + t1 * t1 + t2 * t2) * L;
        }
        float inv = 1.f / den;
        float wn;
        if (iter > 1) {                          // FIX_CLUSTER_POS_ITER = 1
            float x = T0 * inv, y = T1 * inv, zz = T2 * inv;
            float xw = x * x + y * y + zz * zz;
            wn = S2 - (T0 * T0 + T1 * T1 + T2 * T2) * inv;
            g_X[t] = make_float4(x, y, zz, xw);
        } else {
            float4 xo = g_X[t];
            wn = fmaf(den, xo.w, S2) - 2.f * (xo.x * T0 + xo.y * T1 + xo.z * T2);
        }
        g_Q[t] = 3.f * den / (wn + 3.f * den * EPSILON);
    }
    __syncthreads();
    for (int i = t; i < M * KC; i += 256) { g_L[i] = 0.f; g_S2v[i] = 0.f; }
    for (int i = t; i < M * 3 * KC; i += 256) g_W[i] = 0.f;
}

// ---------------- gather outputs: concat(TVs, R, t, X) -------------------
__global__ void k_out(float* out, const float* __restrict__ Vs) {
    int idx = blockIdx.x * 256 + threadIdx.x;
    const int nTV = M * 3 * N, nR = M * 9, nT = M * 3, nX = KC * 3;
    if (idx < nTV) {
        int md = idx / N, n = idx - md * N;
        int m = md / 3, d = md - 3 * m;
        const float* v = Vs + m * 3 * N;
        const float* R = g_R + m * 9 + d * 3;
        out[idx] = fmaf(R[0], v[n], fmaf(R[1], v[N + n], fmaf(R[2], v[2 * N + n], g_t[md])));
    } else if (idx < nTV + nR) out[idx] = g_R[idx - nTV];
    else if (idx < nTV + nR + nT) out[idx] = g_t[idx - nTV - nR];
    else if (idx < nTV + nR + nT + nX) {
        int r = idx - nTV - nR - nT;
        int k = r / 3, d = r - 3 * k;
        float4 xx = g_X[k];
        out[idx] = (d == 0) ? xx.x : ((d == 1) ? xx.y : xx.z);
    }
}

extern "C" void kernel_launch(void* const* d_in, const int* in_sizes, int n_in,
                              void* d_out, int out_size) {
    const float* Vs = (const float*)d_in[0];
    const float* X0 = (const float*)d_in[1];
    const float* Q0 = (const float*)d_in[2];
    float* out = (float*)d_out;

    k_pre<<<25, 256>>>(Vs, X0, Q0);

    for (int i = 0; i < ITERS; i++) {
        k_apass<<<BLKS_PER_M * M, 128>>>(Vs);
        k_solve<<<1, 256>>>(i);
    }
    int total = M * 3 * N + M * 9 + M * 3 + KC * 3;
    k_out<<<(total + 255) / 256, 256>>>(out, Vs);
}

// round 14
// speedup vs baseline: 2.0266x; 1.0335x over previous
#include <cuda_runtime.h>
#include <math.h>

#define M 8
#define N 8192
#define KC 256
#define ITERS 6
#define EPSILON 0.01f
#define GAMMA 0.005f
#define LOG2E 1.4426950408889634f

#define BLKS_PER_M 74           // 74 * 8 = 592 = 4 CTAs on every of 148 SMs
#define WPM (BLKS_PER_M * 4)    // 296 warps per m
#define NREM (N - WPM * 27)     // 200 warps carry 28 points, rest 27
#define MAXC 28

typedef unsigned long long f32x2;

// ---------------- device scratch (static allocation only) ----------------
__device__ float g_L[M * KC];          // sum_n a
__device__ float g_W[M * 3 * KC];      // sum_n a * v   (no Q factor)
__device__ float g_S2v[M * KC];        // sum_n a * |v|^2
__device__ float4 g_X[KC];             // x,y,z,|x|^2
__device__ float g_Q[KC];
__device__ float g_R[M * 9];
__device__ float g_t[M * 3];
__device__ float g_beta;

__device__ __forceinline__ float ex2f(float x) {
    float y;
    asm("ex2.approx.ftz.f32 %0, %1;" : "=f"(y) : "f"(x));
    return y;
}
__device__ __forceinline__ f32x2 pack2(float lo, float hi) {
    f32x2 r;
    asm("mov.b64 %0, {%1, %2};" : "=l"(r) : "f"(lo), "f"(hi));
    return r;
}
__device__ __forceinline__ void unpack2(f32x2 v, float& lo, float& hi) {
    asm("mov.b64 {%0, %1}, %2;" : "=f"(lo), "=f"(hi) : "l"(v));
}
__device__ __forceinline__ f32x2 fma2(f32x2 a, f32x2 b, f32x2 c) {
    f32x2 d;
    asm("fma.rn.f32x2 %0, %1, %2, %3;" : "=l"(d) : "l"(a), "l"(b), "l"(c));
    return d;
}
__device__ __forceinline__ f32x2 add2(f32x2 a, f32x2 b) {
    f32x2 d;
    asm("add.rn.f32x2 %0, %1, %2;" : "=l"(d) : "l"(a), "l"(b));
    return d;
}
__device__ __forceinline__ f32x2 mul2(f32x2 a, f32x2 b) {
    f32x2 d;
    asm("mul.rn.f32x2 %0, %1, %2;" : "=l"(d) : "l"(a), "l"(b));
    return d;
}

#define WSUM(v) do { \
    v += __shfl_xor_sync(0xffffffffu, (v), 16); \
    v += __shfl_xor_sync(0xffffffffu, (v), 8);  \
    v += __shfl_xor_sync(0xffffffffu, (v), 4);  \
    v += __shfl_xor_sync(0xffffffffu, (v), 2);  \
    v += __shfl_xor_sync(0xffffffffu, (v), 1);  \
} while (0)

// ---------------- init ----------------
__global__ void k_pre(const float* Vs, const float* X0, const float* Q0) {
    __shared__ float sh[256];
    int b = blockIdx.x, t = threadIdx.x;
    if (b < 24) {                      // b = m*3+d : mean over n -> g_t
        const float* p = Vs + b * N;
        float s = 0.f;
        for (int n = t; n < N; n += 256) s += p[n];
        sh[t] = s; __syncthreads();
        for (int o = 128; o > 0; o >>= 1) { if (t < o) sh[t] += sh[t + o]; __syncthreads(); }
        if (t == 0) g_t[b] = -sh[0] / (float)N;
    } else {
        float q = (t < KC) ? Q0[t] : 0.f;
        sh[t] = q; __syncthreads();
        for (int o = 128; o > 0; o >>= 1) { if (t < o) sh[t] += sh[t + o]; __syncthreads(); }
        if (t == 0) { float mq = sh[0] / (float)KC; g_beta = GAMMA * mq * sqrtf(mq); }
        if (t < KC) {
            float x = X0[t * 3 + 0], y = X0[t * 3 + 1], z = X0[t * 3 + 2];
            g_X[t] = make_float4(x, y, z, x * x + y * y + z * z);
            g_Q[t] = q;
        }
        if (t < 72) {                  // R = I per m
            int m = t / 9, i = t - 9 * m;
            g_R[t] = (i == 0 || i == 4 || i == 8) ? 1.f : 0.f;
        }
        for (int i = t; i < M * KC; i += 256) { g_L[i] = 0.f; g_S2v[i] = 0.f; }
        for (int i = t; i < M * 3 * KC; i += 256) g_W[i] = 0.f;
    }
}

// ------- a-pass, two-phase, f32x2-packed over cluster pairs (k, k+128) ---
__global__ void __launch_bounds__(128) k_apass(const float* __restrict__ Vs) {
    int lane = threadIdx.x & 31, warp = threadIdx.x >> 5;
    int m = blockIdx.x / BLKS_PER_M;
    int blk = blockIdx.x - m * BLKS_PER_M;
    int gw = blk * 4 + warp;                         // 0..WPM-1
    int cnt = (gw < NREM) ? 28 : 27;
    int start = gw * 27 + min(gw, NREM);

    __shared__ f32x2 sCx[128], sCy[128], sCz[128], sNq[128], sCc[128];
    __shared__ float4 sTV[4 * MAXC]; // (tx, ty, tz, rr) per n
    __shared__ float4 sV[4 * MAXC];  // (v0, v1, v2, vv) per n
    __shared__ float  sInv[4 * MAXC];
    __shared__ float  sh[5 * KC];    // block merge buffer

    // build packed constants: thread t handles pair (t, t+128)
    {
        int k0 = threadIdx.x;        // 128 threads exactly
        float4 xa = g_X[k0];         float4 xb = g_X[k0 + 128];
        float qa = g_Q[k0];          float qb = g_Q[k0 + 128];
        float na = -0.5f * LOG2E * qa, nb = -0.5f * LOG2E * qb;
        sCx[k0] = pack2(-2.f * na * xa.x, -2.f * nb * xb.x);
        sCy[k0] = pack2(-2.f * na * xa.y, -2.f * nb * xb.y);
        sCz[k0] = pack2(-2.f * na * xa.z, -2.f * nb * xb.z);
        sNq[k0] = pack2(na, nb);
        sCc[k0] = pack2(fmaf(na, xa.w, 1.5f * __log2f(qa)),
                        fmaf(nb, xb.w, 1.5f * __log2f(qb)));
    }
    for (int i = threadIdx.x; i < 5 * KC; i += 128) sh[i] = 0.f;
    __syncthreads();

    float beta = g_beta;
    const float* vs = Vs + m * 3 * N;
    const float* Rm = g_R + m * 9;
    float r0 = Rm[0], r1 = Rm[1], r2c = Rm[2], r3 = Rm[3], r4 = Rm[4], r5 = Rm[5],
          r6 = Rm[6], r7 = Rm[7], r8 = Rm[8];
    float tt0 = g_t[m * 3 + 0], tt1 = g_t[m * 3 + 1], tt2 = g_t[m * 3 + 2];

    // ---- Phase A: per-lane n, per-lane denominator over 128 packed pairs ----
    {
        int n = start + min(lane, cnt - 1);          // clamped (no OOB)
        float v0 = vs[n], v1 = vs[N + n], v2 = vs[2 * N + n];
        float tx = fmaf(r0, v0, fmaf(r1, v1, fmaf(r2c, v2, tt0)));
        float ty = fmaf(r3, v0, fmaf(r4, v1, fmaf(r5, v2, tt1)));
        float tz = fmaf(r6, v0, fmaf(r7, v1, fmaf(r8, v2, tt2)));
        float rr = fmaf(tx, tx, fmaf(ty, ty, tz * tz));
        float vv = fmaf(v0, v0, fmaf(v1, v1, v2 * v2));
        f32x2 tx2 = pack2(tx, tx), ty2 = pack2(ty, ty),
              tz2 = pack2(tz, tz), rr2 = pack2(rr, rr);
        float sA0 = 0.f, sA1 = 0.f, sB0 = 0.f, sB1 = 0.f;
#pragma unroll 2
        for (int k0 = 0; k0 < 128; k0 += 2) {
            f32x2 gA = fma2(sCx[k0], tx2, fma2(sCy[k0], ty2,
                        fma2(sCz[k0], tz2, fma2(sNq[k0], rr2, sCc[k0]))));
            f32x2 gB = fma2(sCx[k0 + 1], tx2, fma2(sCy[k0 + 1], ty2,
                        fma2(sCz[k0 + 1], tz2, fma2(sNq[k0 + 1], rr2, sCc[k0 + 1]))));
            float a0, a1, b0, b1;
            unpack2(gA, a0, a1);
            unpack2(gB, b0, b1);
            sA0 += ex2f(a0); sA1 += ex2f(a1);
            sB0 += ex2f(b0); sB1 += ex2f(b1);
        }
        float s = (sA0 + sA1) + (sB0 + sB1);
        if (lane < cnt) {
            int sl = warp * MAXC + lane;
            sTV[sl] = make_float4(tx, ty, tz, rr);
            sV[sl]  = make_float4(v0, v1, v2, vv);
            sInv[sl] = __fdividef(1.f, s + beta);
        }
    }
    __syncwarp();

    // ---- Phase B: two halves, 2 packed pairs per lane per half ----
#pragma unroll 1
    for (int half = 0; half < 2; half++) {
        f32x2 cx2[2], cy2[2], cz2[2], nq2[2], cc2[2];
#pragma unroll
        for (int j = 0; j < 2; j++) {
            int k0 = lane + ((half * 2 + j) << 5);   // 0..127
            cx2[j] = sCx[k0]; cy2[j] = sCy[k0]; cz2[j] = sCz[k0];
            nq2[j] = sNq[k0]; cc2[j] = sCc[k0];
        }
        f32x2 accL2[2], aw02[2], aw12[2], aw22[2], aS2[2];
#pragma unroll
        for (int j = 0; j < 2; j++) {
            accL2[j] = 0ULL; aw02[j] = 0ULL; aw12[j] = 0ULL; aw22[j] = 0ULL; aS2[j] = 0ULL;
        }

#pragma unroll 2
        for (int ni = 0; ni < cnt; ni++) {
            int sl = warp * MAXC + ni;
            float4 tvv = sTV[sl];            // broadcast
            float4 v4  = sV[sl];
            float inv  = sInv[sl];
            f32x2 tx2 = pack2(tvv.x, tvv.x), ty2 = pack2(tvv.y, tvv.y),
                  tz2 = pack2(tvv.z, tvv.z), rr2 = pack2(tvv.w, tvv.w);
            f32x2 v02 = pack2(v4.x, v4.x), v12 = pack2(v4.y, v4.y),
                  v22 = pack2(v4.z, v4.z), vv2 = pack2(v4.w, v4.w);
            f32x2 inv2 = pack2(inv, inv);
#pragma unroll
            for (int j = 0; j < 2; j++) {
                f32x2 arg = fma2(cx2[j], tx2, fma2(cy2[j], ty2,
                            fma2(cz2[j], tz2, fma2(nq2[j], rr2, cc2[j]))));
                float a0, a1;
                unpack2(arg, a0, a1);
                f32x2 av = mul2(pack2(ex2f(a0), ex2f(a1)), inv2);
                accL2[j] = add2(accL2[j], av);
                aw02[j] = fma2(v02, av, aw02[j]);
                aw12[j] = fma2(v12, av, aw12[j]);
                aw22[j] = fma2(v22, av, aw22[j]);
                aS2[j]  = fma2(vv2, av, aS2[j]);
            }
        }
#pragma unroll
        for (int j = 0; j < 2; j++) {
            int k0 = lane + ((half * 2 + j) << 5);
            float lo, hi;
            unpack2(accL2[j], lo, hi);
            atomicAdd(&sh[k0], lo);              atomicAdd(&sh[k0 + 128], hi);
            unpack2(aw02[j], lo, hi);
            atomicAdd(&sh[KC + k0], lo);         atomicAdd(&sh[KC + k0 + 128], hi);
            unpack2(aw12[j], lo, hi);
            atomicAdd(&sh[2 * KC + k0], lo);     atomicAdd(&sh[2 * KC + k0 + 128], hi);
            unpack2(aw22[j], lo, hi);
            atomicAdd(&sh[3 * KC + k0], lo);     atomicAdd(&sh[3 * KC + k0 + 128], hi);
            unpack2(aS2[j], lo, hi);
            atomicAdd(&sh[4 * KC + k0], lo);     atomicAdd(&sh[4 * KC + k0 + 128], hi);
        }
    }
    __syncthreads();

    // ---- global merge ----
    for (int i = threadIdx.x; i < KC; i += 128) {
        atomicAdd(&g_L[m * KC + i], sh[i]);
        atomicAdd(&g_W[(m * 3 + 0) * KC + i], sh[KC + i]);
        atomicAdd(&g_W[(m * 3 + 1) * KC + i], sh[2 * KC + i]);
        atomicAdd(&g_W[(m * 3 + 2) * KC + i], sh[3 * KC + i]);
        atomicAdd(&g_S2v[m * KC + i], sh[4 * KC + i]);
    }
}

// Jacobi rotation with COMPILE-TIME indices (keeps A/V in registers)
#define JROT(P_, Q_) do { \
    float apq = A[P_][Q_]; \
    if (fabsf(apq) > 1e-30f) { \
        float theta = 0.5f * (A[Q_][Q_] - A[P_][P_]) / apq; \
        float tj = copysignf(1.f, theta) / (fabsf(theta) + sqrtf(fmaf(theta, theta, 1.f))); \
        float c = rsqrtf(fmaf(tj, tj, 1.f)); \
        float sj = tj * c; \
        _Pragma("unroll") \
        for (int i_ = 0; i_ < 3; i_++) { \
            float aip = A[i_][P_], aiq = A[i_][Q_]; \
            A[i_][P_] = c * aip - sj * aiq; \
            A[i_][Q_] = sj * aip + c * aiq; \
        } \
        _Pragma("unroll") \
        for (int i_ = 0; i_ < 3; i_++) { \
            float api = A[P_][i_], aqi = A[Q_][i_]; \
            A[P_][i_] = c * api - sj * aqi; \
            A[Q_][i_] = sj * api + c * aqi; \
        } \
        _Pragma("unroll") \
        for (int i_ = 0; i_ < 3; i_++) { \
            float vip = V[i_][P_], viq = V[i_][Q_]; \
            V[i_][P_] = c * vip - sj * viq; \
            V[i_][Q_] = sj * vip + c * viq; \
        } \
    } \
} while (0)

#define VSWAPC(C0_, C1_) do { \
    float tmp_; \
    tmp_ = V[0][C0_]; V[0][C0_] = V[0][C1_]; V[0][C1_] = tmp_; \
    tmp_ = V[1][C0_]; V[1][C0_] = V[1][C1_]; V[1][C1_] = tmp_; \
    tmp_ = V[2][C0_]; V[2][C0_] = V[2][C1_]; V[2][C1_] = tmp_; \
} while (0)

// ---- solve: moments -> SVD -> R,t ; then per-k T/S2 -> X,Q update -------
__global__ void k_solve(int iter) {
    __shared__ float sR[M][9], st[M][3];
    int t = threadIdx.x;
    int lane = t & 31, m = t >> 5;   // warp m handles point set m
    float mW0 = 0, mW1 = 0, mW2 = 0, z = 0, mX0 = 0, mX1 = 0, mX2 = 0;
    float p[9];
#pragma unroll
    for (int i = 0; i < 9; i++) p[i] = 0.f;
#pragma unroll
    for (int j = 0; j < 8; j++) {
        int k = lane + (j << 5);
        float L = g_L[m * KC + k];
        float q = g_Q[k];
        float4 xx = g_X[k];
        float w0 = g_W[(m * 3 + 0) * KC + k] * q;
        float w1 = g_W[(m * 3 + 1) * KC + k] * q;
        float w2 = g_W[(m * 3 + 2) * KC + k] * q;
        mW0 += w0; mW1 += w1; mW2 += w2;
        float b = L * q; z += b;
        mX0 = fmaf(b, xx.x, mX0); mX1 = fmaf(b, xx.y, mX1); mX2 = fmaf(b, xx.z, mX2);
        p[0] = fmaf(w0, xx.x, p[0]); p[1] = fmaf(w1, xx.x, p[1]); p[2] = fmaf(w2, xx.x, p[2]);
        p[3] = fmaf(w0, xx.y, p[3]); p[4] = fmaf(w1, xx.y, p[4]); p[5] = fmaf(w2, xx.y, p[5]);
        p[6] = fmaf(w0, xx.z, p[6]); p[7] = fmaf(w1, xx.z, p[7]); p[8] = fmaf(w2, xx.z, p[8]);
    }
    WSUM(mW0); WSUM(mW1); WSUM(mW2); WSUM(z); WSUM(mX0); WSUM(mX1); WSUM(mX2);
#pragma unroll
    for (int i = 0; i < 9; i++) WSUM(p[i]);

    if (lane == 0) {
        float iz = 1.f / z;
        float mXa[3] = { mX0, mX1, mX2 }, mWa[3] = { mW0, mW1, mW2 };
        float P[3][3];
#pragma unroll
        for (int e = 0; e < 3; e++)
#pragma unroll
            for (int d = 0; d < 3; d++)
                P[e][d] = p[e * 3 + d] - mXa[e] * mWa[d] * iz;
        float A[3][3];
#pragma unroll
        for (int d1 = 0; d1 < 3; d1++)
#pragma unroll
            for (int d2 = 0; d2 < 3; d2++) {
                float s2 = 0.f;
#pragma unroll
                for (int e = 0; e < 3; e++) s2 += P[e][d1] * P[e][d2];
                A[d1][d2] = s2;
            }
        float V[3][3] = { {1, 0, 0}, {0, 1, 0}, {0, 0, 1} };
#pragma unroll
        for (int sweep = 0; sweep < 8; sweep++) {
            JROT(0, 1);
            JROT(0, 2);
            JROT(1, 2);
        }
        float e0 = A[0][0], e1 = A[1][1], e2 = A[2][2];
        if (e0 < e1) { float tm = e0; e0 = e1; e1 = tm; VSWAPC(0, 1); }
        if (e1 < e2) { float tm = e1; e1 = e2; e2 = tm; VSWAPC(1, 2); }
        if (e0 < e1) { float tm = e0; e0 = e1; e1 = tm; VSWAPC(0, 1); }
        float det = V[0][0] * (V[1][1] * V[2][2] - V[1][2] * V[2][1])
                  - V[0][1] * (V[1][0] * V[2][2] - V[1][2] * V[2][0])
                  + V[0][2] * (V[1][0] * V[2][1] - V[1][1] * V[2][0]);
        if (det < 0.f) { V[0][2] = -V[0][2]; V[1][2] = -V[1][2]; V[2][2] = -V[2][2]; }
        float u1[3], u2[3], u3[3];
#pragma unroll
        for (int e = 0; e < 3; e++) {
            u1[e] = P[e][0] * V[0][0] + P[e][1] * V[1][0] + P[e][2] * V[2][0];
            u2[e] = P[e][0] * V[0][1] + P[e][1] * V[1][1] + P[e][2] * V[2][1];
        }
        float n1 = rsqrtf(u1[0] * u1[0] + u1[1] * u1[1] + u1[2] * u1[2]);
#pragma unroll
        for (int e = 0; e < 3; e++) u1[e] *= n1;
        float d12 = u1[0] * u2[0] + u1[1] * u2[1] + u1[2] * u2[2];
#pragma unroll
        for (int e = 0; e < 3; e++) u2[e] -= d12 * u1[e];
        float n2 = rsqrtf(u2[0] * u2[0] + u2[1] * u2[1] + u2[2] * u2[2]);
#pragma unroll
        for (int e = 0; e < 3; e++) u2[e] *= n2;
        u3[0] = u1[1] * u2[2] - u1[2] * u2[1];
        u3[1] = u1[2] * u2[0] - u1[0] * u2[2];
        u3[2] = u1[0] * u2[1] - u1[1] * u2[0];
        float R[9];
#pragma unroll
        for (int i = 0; i < 3; i++)
#pragma unroll
            for (int jj = 0; jj < 3; jj++)
                R[i * 3 + jj] = u1[i] * V[jj][0] + u2[i] * V[jj][1] + u3[i] * V[jj][2];
#pragma unroll
        for (int i = 0; i < 9; i++) { g_R[m * 9 + i] = R[i]; sR[m][i] = R[i]; }
#pragma unroll
        for (int i = 0; i < 3; i++) {
            float tv = (mXa[i] - (R[i * 3 + 0] * mW0 + R[i * 3 + 1] * mW1 + R[i * 3 + 2] * mW2)) * iz;
            g_t[m * 3 + i] = tv; st[m][i] = tv;
        }
    }
    __syncthreads();

    // ---- per-k: den, T = sum_m (R Wraw + t L), S2; then X/Q update ----
    if (t < KC) {
        float den = 0.f, T0 = 0.f, T1 = 0.f, T2 = 0.f, S2 = 0.f;
#pragma unroll
        for (int mm = 0; mm < M; mm++) {
            float L  = g_L[mm * KC + t];
            float w0 = g_W[(mm * 3 + 0) * KC + t];
            float w1 = g_W[(mm * 3 + 1) * KC + t];
            float w2 = g_W[(mm * 3 + 2) * KC + t];
            float s2v = g_S2v[mm * KC + t];
            float t0 = st[mm][0], t1 = st[mm][1], t2 = st[mm][2];
            float rw0 = sR[mm][0] * w0 + sR[mm][1] * w1 + sR[mm][2] * w2;
            float rw1 = sR[mm][3] * w0 + sR[mm][4] * w1 + sR[mm][5] * w2;
            float rw2 = sR[mm][6] * w0 + sR[mm][7] * w1 + sR[mm][8] * w2;
            den += L;
            T0 += rw0 + t0 * L; T1 += rw1 + t1 * L; T2 += rw2 + t2 * L;
            S2 += s2v + 2.f * (t0 * rw0 + t1 * rw1 + t2 * rw2)
                + (t0 * t0 + t1 * t1 + t2 * t2) * L;
        }
        float inv = 1.f / den;
        float wn;
        if (iter > 1) {                          // FIX_CLUSTER_POS_ITER = 1
            float x = T0 * inv, y = T1 * inv, zz = T2 * inv;
            float xw = x * x + y * y + zz * zz;
            wn = S2 - (T0 * T0 + T1 * T1 + T2 * T2) * inv;
            g_X[t] = make_float4(x, y, zz, xw);
        } else {
            float4 xo = g_X[t];
            wn = fmaf(den, xo.w, S2) - 2.f * (xo.x * T0 + xo.y * T1 + xo.z * T2);
        }
        g_Q[t] = 3.f * den / (wn + 3.f * den * EPSILON);
    }
    __syncthreads();
    for (int i = t; i < M * KC; i += 256) { g_L[i] = 0.f; g_S2v[i] = 0.f; }
    for (int i = t; i < M * 3 * KC; i += 256) g_W[i] = 0.f;
}

// ---------------- gather outputs: concat(TVs, R, t, X) -------------------
__global__ void k_out(float* out, const float* __restrict__ Vs) {
    int idx = blockIdx.x * 256 + threadIdx.x;
    const int nTV = M * 3 * N, nR = M * 9, nT = M * 3, nX = KC * 3;
    if (idx < nTV) {
        int md = idx / N, n = idx - md * N;
        int m = md / 3, d = md - 3 * m;
        const float* v = Vs + m * 3 * N;
        const float* R = g_R + m * 9 + d * 3;
        out[idx] = fmaf(R[0], v[n], fmaf(R[1], v[N + n], fmaf(R[2], v[2 * N + n], g_t[md])));
    } else if (idx < nTV + nR) out[idx] = g_R[idx - nTV];
    else if (idx < nTV + nR + nT) out[idx] = g_t[idx - nTV - nR];
    else if (idx < nTV + nR + nT + nX) {
        int r = idx - nTV - nR - nT;
        int k = r / 3, d = r - 3 * k;
        float4 xx = g_X[k];
        out[idx] = (d == 0) ? xx.x : ((d == 1) ? xx.y : xx.z);
    }
}

extern "C" void kernel_launch(void* const* d_in, const int* in_sizes, int n_in,
                              void* d_out, int out_size) {
    const float* Vs = (const float*)d_in[0];
    const float* X0 = (const float*)d_in[1];
    const float* Q0 = (const float*)d_in[2];
    float* out = (float*)d_out;

    k_pre<<<25, 256>>>(Vs, X0, Q0);

    for (int i = 0; i < ITERS; i++) {
        k_apass<<<BLKS_PER_M * M, 128>>>(Vs);
        k_solve<<<1, 256>>>(i);
    }
    int total = M * 3 * N + M * 9 + M * 3 + KC * 3;
    k_out<<<(total + 255) / 256, 256>>>(out, Vs);
}